// round 1
// baseline (speedup 1.0000x reference)
#include <cuda_runtime.h>
#include <math.h>

#define B_   16
#define C_   256
#define HH   64
#define WW   64
#define HWP  4096      // H*W
#define CO   768       // 3*C
#define NH   8
#define HS   32

// 201 MB scratch for q,k,v (post PE/modulation), layout [B][768][4096]
__device__ float g_qkv[(size_t)B_ * CO * HWP];

// ---------------- packed f32x2 helpers (sm_100+) ----------------
__device__ __forceinline__ unsigned long long pack2(float lo, float hi) {
    unsigned long long r;
    asm("mov.b64 %0, {%1, %2};" : "=l"(r) : "f"(lo), "f"(hi));
    return r;
}
__device__ __forceinline__ void unpack2(unsigned long long v, float& lo, float& hi) {
    asm("mov.b64 {%0, %1}, %2;" : "=f"(lo), "=f"(hi) : "l"(v));
}
__device__ __forceinline__ unsigned long long ffma2(unsigned long long a,
                                                    unsigned long long b,
                                                    unsigned long long c) {
    unsigned long long d;
    asm("fma.rn.f32x2 %0, %1, %2, %3;" : "=l"(d) : "l"(a), "l"(b), "l"(c));
    return d;
}

__device__ __forceinline__ float silu_f(float v) {
    return v / (1.0f + expf(-v));
}

// ---------------- Kernel 1: silu -> output channels [0,256) ----------------
__global__ void silu_kernel(const float* __restrict__ x,
                            const float* __restrict__ pre_act_bias,
                            float* __restrict__ out) {
    int i = blockIdx.x * blockDim.x + threadIdx.x;   // float4 index; total 4194304
    const float4* x4 = (const float4*)x;
    float4 v = x4[i];
    int w4 = i & 1023;            // (HWP/4)=1024 float4 per (b,c) row
    int c  = (i >> 10) & 255;
    int b  = i >> 18;             // / (256*1024)
    float pb = pre_act_bias[c];
    float4 r;
    r.x = silu_f(v.x + pb);
    r.y = silu_f(v.y + pb);
    r.z = silu_f(v.z + pb);
    r.w = silu_f(v.w + pb);
    ((float4*)out)[(size_t)b * (512 * 1024) + c * 1024 + w4] = r;
}

// ---------------- Kernel 2: QKV GEMM + PE + FiLM epilogue ----------------
// Per batch: qkv[o,p] = sum_c W[o,c]*(xp[c,p]+pqb[c]) ; epilogue per section.
#define BM 128
#define BN 128
#define BK 16

__global__ __launch_bounds__(256, 2)
void qkv_gemm_kernel(const float* __restrict__ W,       // [768,256]
                     const float* __restrict__ outbuf,  // xp lives in out[:, 0:256]
                     const float* __restrict__ qkv_b,
                     const float* __restrict__ pqb,
                     const float* __restrict__ pe_q_h, const float* __restrict__ pe_q_w,
                     const float* __restrict__ pe_k_h, const float* __restrict__ pe_k_w,
                     const float* __restrict__ mod_mult, const float* __restrict__ mod_bias) {
    __shared__ float As[BK][BM + 1];                      // stride 129, scalar access
    __shared__ __align__(16) float Bs[BK][BN + 4];        // stride 132 (16B aligned rows)

    const int b  = blockIdx.z;
    const int m0 = blockIdx.y * BM;
    const int n0 = blockIdx.x * BN;
    const float* Xp  = outbuf + (size_t)b * 512 * HWP;    // channels 0..255 of out
    float*       Out = g_qkv + (size_t)b * CO * HWP;

    const int tid = threadIdx.x;
    const int ty  = tid >> 4;    // 0..15
    const int tx  = tid & 15;    // 0..15

    unsigned long long acc[8][4];
#pragma unroll
    for (int i = 0; i < 8; i++)
#pragma unroll
        for (int j = 0; j < 4; j++) acc[i][j] = pack2(0.f, 0.f);

    for (int k0 = 0; k0 < C_; k0 += BK) {
        // load A tile [128 x 16], store transposed
#pragma unroll
        for (int i = 0; i < 2; i++) {
            int f  = tid + i * 256;
            int r  = f >> 2;
            int c4 = (f & 3) * 4;
            float4 av = *(const float4*)(W + (size_t)(m0 + r) * C_ + k0 + c4);
            As[c4 + 0][r] = av.x; As[c4 + 1][r] = av.y;
            As[c4 + 2][r] = av.z; As[c4 + 3][r] = av.w;
        }
        // load B tile [16 x 128] (+ pre_qkv_bias)
#pragma unroll
        for (int i = 0; i < 2; i++) {
            int f  = tid + i * 256;
            int r  = f >> 5;
            int c4 = (f & 31) * 4;
            int ch = k0 + r;
            float4 bv = *(const float4*)(Xp + (size_t)ch * HWP + n0 + c4);
            float pb = pqb[ch];
            bv.x += pb; bv.y += pb; bv.z += pb; bv.w += pb;
            *(float4*)&Bs[r][c4] = bv;
        }
        __syncthreads();

#pragma unroll
        for (int k = 0; k < BK; k++) {
            unsigned long long ap[8];
#pragma unroll
            for (int i = 0; i < 8; i++) {
                float a = As[k][ty * 8 + i];
                ap[i] = pack2(a, a);
            }
            const unsigned long long* bp =
                (const unsigned long long*)&Bs[k][tx * 8];
            unsigned long long bv[4];
#pragma unroll
            for (int j = 0; j < 4; j++) bv[j] = bp[j];
#pragma unroll
            for (int i = 0; i < 8; i++)
#pragma unroll
                for (int j = 0; j < 4; j++) acc[i][j] = ffma2(ap[i], bv[j], acc[i][j]);
        }
        __syncthreads();
    }

    // epilogue
    const int col0 = n0 + tx * 8;
    const int y    = col0 >> 6;      // 8 cols never cross a W=64 boundary
    const int xw0  = col0 & 63;
#pragma unroll
    for (int i = 0; i < 8; i++) {
        int o = m0 + ty * 8 + i;
        float vals[8];
#pragma unroll
        for (int j = 0; j < 4; j++) unpack2(acc[i][j], vals[2 * j], vals[2 * j + 1]);
        float qb = qkv_b[o];
        if (o < 256) {                 // q: +PE, then FiLM
            int c = o;
            float mm = mod_mult[b * 256 + c];
            float mb = mod_bias[b * 256 + c];
            float ph = pe_q_h[c * 64 + y];
#pragma unroll
            for (int j = 0; j < 8; j++)
                vals[j] = (vals[j] + qb + ph + pe_q_w[c * 64 + xw0 + j]) * mm + mb;
        } else if (o < 512) {          // k: +PE
            int c = o - 256;
            float ph = pe_k_h[c * 64 + y];
#pragma unroll
            for (int j = 0; j < 8; j++)
                vals[j] += qb + ph + pe_k_w[c * 64 + xw0 + j];
        } else {                       // v
#pragma unroll
            for (int j = 0; j < 8; j++) vals[j] += qb;
        }
        float* op = Out + (size_t)o * HWP + col0;
        *(float4*)(op)     = make_float4(vals[0], vals[1], vals[2], vals[3]);
        *(float4*)(op + 4) = make_float4(vals[4], vals[5], vals[6], vals[7]);
    }
}

// ---------------- Kernel 3: channel attention per (b,h) ----------------
#define NT  128
#define NTP 129

__global__ __launch_bounds__(256)
void attn_kernel(float* __restrict__ out) {
    __shared__ float qs[HS][NTP];
    __shared__ float ks[HS][NTP];
    __shared__ float ls[HS][HS + 1];

    const int bh = blockIdx.x;
    const int b  = bh >> 3;
    const int h  = bh & 7;
    const float* qg = g_qkv + (size_t)b * CO * HWP + (size_t)(h * HS) * HWP;
    const float* kg = qg + (size_t)256 * HWP;
    const float* vg = qg + (size_t)512 * HWP;

    const int tid = threadIdx.x;
    const int cc  = tid >> 4;      // 0..15
    const int dd  = tid & 15;      // 0..15
    const int c0  = 2 * cc, d0 = 2 * dd;

    float a00 = 0.f, a01 = 0.f, a10 = 0.f, a11 = 0.f;

    // ---- phase 1: logits = Q K^T over n ----
    for (int n0 = 0; n0 < HWP; n0 += NT) {
#pragma unroll
        for (int i = 0; i < 4; i++) {
            int f  = tid + i * 256;
            int r  = f >> 5;
            int c4 = (f & 31) * 4;
            float4 qv = *(const float4*)(qg + (size_t)r * HWP + n0 + c4);
            qs[r][c4 + 0] = qv.x; qs[r][c4 + 1] = qv.y;
            qs[r][c4 + 2] = qv.z; qs[r][c4 + 3] = qv.w;
            float4 kv = *(const float4*)(kg + (size_t)r * HWP + n0 + c4);
            ks[r][c4 + 0] = kv.x; ks[r][c4 + 1] = kv.y;
            ks[r][c4 + 2] = kv.z; ks[r][c4 + 3] = kv.w;
        }
        __syncthreads();
#pragma unroll 4
        for (int n = 0; n < NT; n++) {
            float q0 = qs[c0][n], q1 = qs[c0 + 1][n];
            float k0 = ks[d0][n], k1 = ks[d0 + 1][n];
            a00 += q0 * k0; a01 += q0 * k1;
            a10 += q1 * k0; a11 += q1 * k1;
        }
        __syncthreads();
    }
    ls[c0][d0] = a00;     ls[c0][d0 + 1] = a01;
    ls[c0 + 1][d0] = a10; ls[c0 + 1][d0 + 1] = a11;
    __syncthreads();

    // ---- phase 2: softmax over d (rows c), scaled by 1/sqrt(32) ----
    {
        const int wid = tid >> 5, lane = tid & 31;
        const float rscale = 0.17677669529663687f;   // 1/sqrt(32)
#pragma unroll
        for (int r = wid * 4; r < wid * 4 + 4; r++) {
            float v = ls[r][lane] * rscale;
            float mx = v;
#pragma unroll
            for (int o = 16; o > 0; o >>= 1) mx = fmaxf(mx, __shfl_xor_sync(0xffffffffu, mx, o));
            float e = expf(v - mx);
            float s = e;
#pragma unroll
            for (int o = 16; o > 0; o >>= 1) s += __shfl_xor_sync(0xffffffffu, s, o);
            ls[r][lane] = e / s;
        }
    }
    __syncthreads();

    // ---- phase 3: out = W V ----
    const int c  = tid >> 3;   // 0..31
    const int ng = tid & 7;    // 0..7
    float wreg[32];
#pragma unroll
    for (int d = 0; d < 32; d++) wreg[d] = ls[c][d];
    float* og = out + (size_t)b * 512 * HWP + (size_t)(256 + h * HS + c) * HWP;

    for (int n0 = 0; n0 < HWP; n0 += NT) {
#pragma unroll
        for (int i = 0; i < 4; i++) {
            int f  = tid + i * 256;
            int r  = f >> 5;
            int c4 = (f & 31) * 4;
            float4 vv = *(const float4*)(vg + (size_t)r * HWP + n0 + c4);
            qs[r][c4 + 0] = vv.x; qs[r][c4 + 1] = vv.y;
            qs[r][c4 + 2] = vv.z; qs[r][c4 + 3] = vv.w;
        }
        __syncthreads();
#pragma unroll
        for (int it = 0; it < NT / 8; it++) {
            int n = it * 8 + ng;
            float s = 0.f;
#pragma unroll
            for (int d = 0; d < 32; d++) s += wreg[d] * qs[d][n];
            og[n0 + n] = s;
        }
        __syncthreads();
    }
}

// ---------------- launcher ----------------
extern "C" void kernel_launch(void* const* d_in, const int* in_sizes, int n_in,
                              void* d_out, int out_size) {
    const float* x        = (const float*)d_in[0];
    const float* mod_mult = (const float*)d_in[1];
    const float* mod_bias = (const float*)d_in[2];
    const float* qkv_w    = (const float*)d_in[3];
    const float* qkv_b    = (const float*)d_in[4];
    const float* pe_q_h   = (const float*)d_in[5];
    const float* pe_q_w   = (const float*)d_in[6];
    const float* pe_k_h   = (const float*)d_in[7];
    const float* pe_k_w   = (const float*)d_in[8];
    const float* pab      = (const float*)d_in[9];
    const float* pqb      = (const float*)d_in[10];
    float* out = (float*)d_out;

    // 1) silu -> out[:, 0:256]
    silu_kernel<<<16384, 256>>>(x, pab, out);

    // 2) per-batch QKV GEMM with fused PE/FiLM epilogue -> g_qkv
    dim3 g2(HWP / BN, CO / BM, B_);   // (32, 6, 16)
    qkv_gemm_kernel<<<g2, 256>>>(qkv_w, out, qkv_b, pqb,
                                 pe_q_h, pe_q_w, pe_k_h, pe_k_w,
                                 mod_mult, mod_bias);

    // 3) channel attention -> out[:, 256:512]
    attn_kernel<<<B_ * NH, 256>>>(out);
}

// round 3
// speedup vs baseline: 1.4455x; 1.4455x over previous
#include <cuda_runtime.h>
#include <cuda_bf16.h>
#include <math.h>
#include <stdint.h>

#define B_   16
#define C_   256
#define HH   64
#define WW   64
#define HWP  4096      // H*W
#define CO   768       // 3*C
#define NH   8
#define HS   32

// scratch
__device__ float          g_qkv[(size_t)B_ * CO * HWP];      // q,k,v post-epilogue
__device__ __nv_bfloat16  g_xh[(size_t)B_ * HWP * C_];       // x_preact hi, [b][p][c]
__device__ __nv_bfloat16  g_xl[(size_t)B_ * HWP * C_];       // x_preact lo
__device__ __nv_bfloat16  g_wh[(size_t)CO * C_];
__device__ __nv_bfloat16  g_wl[(size_t)CO * C_];
__device__ float          g_biasH[(size_t)CO * HH];          // qkv_b + W@pqb + pe_h
__device__ float          g_peW[(size_t)CO * WW];            // pe_w (0 for v)

__device__ __forceinline__ uint32_t smem_u32(const void* p) {
    uint32_t a;
    asm("{ .reg .u64 t; cvta.to.shared.u64 t, %1; cvt.u32.u64 %0, t; }" : "=r"(a) : "l"(p));
    return a;
}
__device__ __forceinline__ void ldsm_x4(uint32_t* r, uint32_t addr) {
    asm volatile("ldmatrix.sync.aligned.m8n8.x4.shared.b16 {%0,%1,%2,%3}, [%4];"
        : "=r"(r[0]), "=r"(r[1]), "=r"(r[2]), "=r"(r[3]) : "r"(addr));
}
__device__ __forceinline__ void mma_bf16(float* c, const uint32_t* a, const uint32_t* b) {
    asm volatile("mma.sync.aligned.m16n8k16.row.col.f32.bf16.bf16.f32 "
        "{%0,%1,%2,%3}, {%4,%5,%6,%7}, {%8,%9}, {%0,%1,%2,%3};"
        : "+f"(c[0]), "+f"(c[1]), "+f"(c[2]), "+f"(c[3])
        : "r"(a[0]), "r"(a[1]), "r"(a[2]), "r"(a[3]), "r"(b[0]), "r"(b[1]));
}

__device__ __forceinline__ float silu_f(float v) { return v / (1.0f + expf(-v)); }

// ---------------- Kernel 1: silu -> out[:,0:256] fp32  +  bf16 hi/lo transposed ----------------
__global__ __launch_bounds__(256)
void silu_split_kernel(const float* __restrict__ x, const float* __restrict__ pab,
                       float* __restrict__ out,
                       __nv_bfloat16* __restrict__ xh, __nv_bfloat16* __restrict__ xl) {
    __shared__ float s[64][65];
    const int bid = blockIdx.x;
    const int p0 = (bid & 63) * 64;
    const int c0 = ((bid >> 6) & 3) * 64;
    const int b  = bid >> 8;
    const int tid = threadIdx.x;
#pragma unroll
    for (int ii = 0; ii < 4; ii++) {
        int lin = tid + ii * 256;
        int r = lin >> 4;                // c row 0..63
        int u = lin & 15;                // float4 col
        float4 v = *(const float4*)(x + (size_t)(b * 256 + c0 + r) * HWP + p0 + u * 4);
        float pb = pab[c0 + r];
        float4 o;
        o.x = silu_f(v.x + pb); o.y = silu_f(v.y + pb);
        o.z = silu_f(v.z + pb); o.w = silu_f(v.w + pb);
        *(float4*)(out + (size_t)(b * 512 + c0 + r) * HWP + p0 + u * 4) = o;
        s[r][u * 4 + 0] = o.x; s[r][u * 4 + 1] = o.y;
        s[r][u * 4 + 2] = o.z; s[r][u * 4 + 3] = o.w;
    }
    __syncthreads();
#pragma unroll
    for (int ii = 0; ii < 4; ii++) {
        int lin = tid + ii * 256;
        int r = lin >> 4;                // p row 0..63
        int u = lin & 15;                // c 4-chunk
        float v[4];
#pragma unroll
        for (int j = 0; j < 4; j++) v[j] = s[u * 4 + j][r];
        __nv_bfloat16 h[4], l[4];
#pragma unroll
        for (int j = 0; j < 4; j++) {
            h[j] = __float2bfloat16(v[j]);
            l[j] = __float2bfloat16(v[j] - __bfloat162float(h[j]));
        }
        size_t base = (size_t)(b * HWP + p0 + r) * C_ + c0 + u * 4;
        __nv_bfloat162 hh0 = {h[0], h[1]}, hh1 = {h[2], h[3]};
        __nv_bfloat162 ll0 = {l[0], l[1]}, ll1 = {l[2], l[3]};
        *(uint2*)(xh + base) = make_uint2(*(uint32_t*)&hh0, *(uint32_t*)&hh1);
        *(uint2*)(xl + base) = make_uint2(*(uint32_t*)&ll0, *(uint32_t*)&ll1);
    }
}

// ---------------- Kernel 2: prep — W split + fold biases/PE ----------------
__global__ __launch_bounds__(64)
void prep_kernel(const float* __restrict__ W, const float* __restrict__ qkv_b,
                 const float* __restrict__ pqb,
                 const float* __restrict__ peqh, const float* __restrict__ peqw,
                 const float* __restrict__ pekh, const float* __restrict__ pekw,
                 __nv_bfloat16* __restrict__ wh, __nv_bfloat16* __restrict__ wl,
                 float* __restrict__ biasH, float* __restrict__ peW) {
    const int o = blockIdx.x;
    const int t = threadIdx.x;
    __shared__ float red[2];
    float part = 0.f;
#pragma unroll
    for (int j = 0; j < 4; j++) {
        int c = t * 4 + j;
        float w = W[(size_t)o * C_ + c];
        __nv_bfloat16 h = __float2bfloat16(w);
        __nv_bfloat16 l = __float2bfloat16(w - __bfloat162float(h));
        wh[(size_t)o * C_ + c] = h;
        wl[(size_t)o * C_ + c] = l;
        part += w * pqb[c];
    }
#pragma unroll
    for (int off = 16; off > 0; off >>= 1) part += __shfl_xor_sync(0xffffffffu, part, off);
    if ((t & 31) == 0) red[t >> 5] = part;
    __syncthreads();
    float base = qkv_b[o] + red[0] + red[1];
    int y = t;
    float bh, pw;
    if (o < 256)      { bh = base + peqh[o * 64 + y];          pw = peqw[o * 64 + y]; }
    else if (o < 512) { int c = o - 256; bh = base + pekh[c * 64 + y]; pw = pekw[c * 64 + y]; }
    else              { bh = base; pw = 0.f; }
    biasH[o * 64 + y] = bh;
    peW[o * 64 + y]   = pw;
}

// ---------------- Kernel 3: mma.sync bf16 split GEMM + fused epilogue ----------------
// D[o, p] = sum_c W[o,c] * xT[p,c]   via Wh*xh + Wh*xl + Wl*xh
// A = W tiles (row-major [o][c]), B = x tiles ([p][c], n-major => col-major k x n)
#define KC       64
#define SROW     72                         // padded row in bf16 elems (144 B)
#define TILE_E   (128 * SROW)               // elems per tile
#define TILE_BYT (TILE_E * 2)               // 18432 B
#define GSMEM    (4 * TILE_BYT)             // Ah, Al, Bh, Bl = 73728 B

__device__ __forceinline__ void load_tile(char* sm, const __nv_bfloat16* g, int tid) {
#pragma unroll
    for (int ii = 0; ii < 4; ii++) {
        int lin = tid + ii * 256;            // 0..1023
        int r = lin >> 3;                    // row 0..127
        int u = lin & 7;                     // 16B unit
        uint4 v = *(const uint4*)(g + (size_t)r * C_ + u * 8);
        *(uint4*)(sm + r * 144 + u * 16) = v;
    }
}

__global__ __launch_bounds__(256, 1)
void qkv_gemm_mma(const __nv_bfloat16* __restrict__ xh, const __nv_bfloat16* __restrict__ xl,
                  const __nv_bfloat16* __restrict__ wh, const __nv_bfloat16* __restrict__ wl,
                  const float* __restrict__ biasH, const float* __restrict__ peW,
                  const float* __restrict__ mod_mult, const float* __restrict__ mod_bias,
                  float* __restrict__ qkv) {
    extern __shared__ __align__(16) char dyn[];
    char* sAh = dyn;
    char* sAl = dyn + TILE_BYT;
    char* sBh = dyn + 2 * TILE_BYT;
    char* sBl = dyn + 3 * TILE_BYT;
    const uint32_t uAh = smem_u32(sAh), uAl = smem_u32(sAl);
    const uint32_t uBh = smem_u32(sBh), uBl = smem_u32(sBl);

    const int p0 = blockIdx.x * 128;         // positions
    const int o0 = blockIdx.y * 128;         // outputs
    const int b  = blockIdx.z;
    const int tid = threadIdx.x, wid = tid >> 5, lane = tid & 31;
    const int warp_m = (wid & 1) * 64;       // o offset within tile
    const int warp_n = (wid >> 1) * 32;      // p offset within tile

    float c[4][4][4];
#pragma unroll
    for (int i = 0; i < 4; i++)
#pragma unroll
        for (int j = 0; j < 4; j++)
#pragma unroll
            for (int q = 0; q < 4; q++) c[i][j][q] = 0.f;

    // ldmatrix lane offsets (bytes)
    const uint32_t a_lrow = (uint32_t)(lane & 15) * 144 + (uint32_t)(lane >> 4) * 16;
    const uint32_t b_lrow = (uint32_t)(((lane >> 4) << 3) + (lane & 7)) * 144
                          + (uint32_t)((lane >> 3) & 1) * 16;

    const __nv_bfloat16* gAh = wh + (size_t)o0 * C_;
    const __nv_bfloat16* gAl = wl + (size_t)o0 * C_;
    const __nv_bfloat16* gBh = xh + (size_t)(b * HWP + p0) * C_;
    const __nv_bfloat16* gBl = xl + (size_t)(b * HWP + p0) * C_;

    for (int ch = 0; ch < 4; ch++) {
        load_tile(sAh, gAh + ch * KC, tid);
        load_tile(sAl, gAl + ch * KC, tid);
        load_tile(sBh, gBh + ch * KC, tid);
        load_tile(sBl, gBl + ch * KC, tid);
        __syncthreads();

#pragma unroll
        for (int ks = 0; ks < 4; ks++) {
            uint32_t ah[4][4], al[4][4], bh[4][2], bl[4][2];
#pragma unroll
            for (int mt = 0; mt < 4; mt++) {
                uint32_t ra = (uint32_t)(warp_m + mt * 16) * 144 + ks * 32;
                ldsm_x4(ah[mt], uAh + ra + a_lrow);
                ldsm_x4(al[mt], uAl + ra + a_lrow);
            }
#pragma unroll
            for (int nt2 = 0; nt2 < 2; nt2++) {
                uint32_t rb = (uint32_t)(warp_n + nt2 * 16) * 144 + ks * 32;
                uint32_t t0[4], t1[4];
                ldsm_x4(t0, uBh + rb + b_lrow);
                ldsm_x4(t1, uBl + rb + b_lrow);
                bh[nt2 * 2][0] = t0[0]; bh[nt2 * 2][1] = t0[1];
                bh[nt2 * 2 + 1][0] = t0[2]; bh[nt2 * 2 + 1][1] = t0[3];
                bl[nt2 * 2][0] = t1[0]; bl[nt2 * 2][1] = t1[1];
                bl[nt2 * 2 + 1][0] = t1[2]; bl[nt2 * 2 + 1][1] = t1[3];
            }
#pragma unroll
            for (int mt = 0; mt < 4; mt++)
#pragma unroll
                for (int nt = 0; nt < 4; nt++) {
                    mma_bf16(c[mt][nt], ah[mt], bh[nt]);
                    mma_bf16(c[mt][nt], ah[mt], bl[nt]);
                    mma_bf16(c[mt][nt], al[mt], bh[nt]);
                }
        }
        __syncthreads();
    }

    // epilogue: c[mt][nt] -> (o = o0+warp_m+mt*16+g(+8), p = p0+warp_n+nt*8+2t(+1))
    const int g  = lane >> 2;
    const int t  = lane & 3;
    const bool isQ = (o0 < 256);
#pragma unroll
    for (int mt = 0; mt < 4; mt++) {
#pragma unroll
        for (int nt = 0; nt < 4; nt++) {
            int p  = p0 + warp_n + nt * 8 + 2 * t;
            int y  = p >> 6;
            int xw = p & 63;
#pragma unroll
            for (int half = 0; half < 2; half++) {
                int o = o0 + warp_m + mt * 16 + g + half * 8;
                float bias = biasH[o * 64 + y];
                float v0 = c[mt][nt][half * 2 + 0] + bias + peW[o * 64 + xw];
                float v1 = c[mt][nt][half * 2 + 1] + bias + peW[o * 64 + xw + 1];
                if (isQ) {
                    float mm = mod_mult[b * 256 + o];
                    float mb = mod_bias[b * 256 + o];
                    v0 = fmaf(v0, mm, mb);
                    v1 = fmaf(v1, mm, mb);
                }
                *(float2*)(qkv + ((size_t)b * CO + o) * HWP + p) = make_float2(v0, v1);
            }
        }
    }
}

// ---------------- Kernel 4: channel attention per (b,h) ----------------
#define NT  128
#define NTP 129

__global__ __launch_bounds__(256)
void attn_kernel(float* __restrict__ out) {
    __shared__ float qs[HS][NTP];
    __shared__ float ks[HS][NTP];
    __shared__ float ls[HS][HS + 1];

    const int bh = blockIdx.x;
    const int b  = bh >> 3;
    const int h  = bh & 7;
    const float* qg = g_qkv + (size_t)b * CO * HWP + (size_t)(h * HS) * HWP;
    const float* kg = qg + (size_t)256 * HWP;
    const float* vg = qg + (size_t)512 * HWP;

    const int tid = threadIdx.x;
    const int cc  = tid >> 4;
    const int dd  = tid & 15;
    const int c0  = 2 * cc, d0 = 2 * dd;

    float a00 = 0.f, a01 = 0.f, a10 = 0.f, a11 = 0.f;

    for (int n0 = 0; n0 < HWP; n0 += NT) {
#pragma unroll
        for (int i = 0; i < 4; i++) {
            int f  = tid + i * 256;
            int r  = f >> 5;
            int c4 = (f & 31) * 4;
            float4 qv = *(const float4*)(qg + (size_t)r * HWP + n0 + c4);
            qs[r][c4 + 0] = qv.x; qs[r][c4 + 1] = qv.y;
            qs[r][c4 + 2] = qv.z; qs[r][c4 + 3] = qv.w;
            float4 kv = *(const float4*)(kg + (size_t)r * HWP + n0 + c4);
            ks[r][c4 + 0] = kv.x; ks[r][c4 + 1] = kv.y;
            ks[r][c4 + 2] = kv.z; ks[r][c4 + 3] = kv.w;
        }
        __syncthreads();
#pragma unroll 4
        for (int n = 0; n < NT; n++) {
            float q0 = qs[c0][n], q1 = qs[c0 + 1][n];
            float k0 = ks[d0][n], k1 = ks[d0 + 1][n];
            a00 += q0 * k0; a01 += q0 * k1;
            a10 += q1 * k0; a11 += q1 * k1;
        }
        __syncthreads();
    }
    ls[c0][d0] = a00;     ls[c0][d0 + 1] = a01;
    ls[c0 + 1][d0] = a10; ls[c0 + 1][d0 + 1] = a11;
    __syncthreads();

    {
        const int wid = tid >> 5, lane = tid & 31;
        const float rscale = 0.17677669529663687f;
#pragma unroll
        for (int r = wid * 4; r < wid * 4 + 4; r++) {
            float v = ls[r][lane] * rscale;
            float mx = v;
#pragma unroll
            for (int o = 16; o > 0; o >>= 1) mx = fmaxf(mx, __shfl_xor_sync(0xffffffffu, mx, o));
            float e = expf(v - mx);
            float s = e;
#pragma unroll
            for (int o = 16; o > 0; o >>= 1) s += __shfl_xor_sync(0xffffffffu, s, o);
            ls[r][lane] = e / s;
        }
    }
    __syncthreads();

    const int c  = tid >> 3;
    const int ng = tid & 7;
    float wreg[32];
#pragma unroll
    for (int d = 0; d < 32; d++) wreg[d] = ls[c][d];
    float* og = out + (size_t)b * 512 * HWP + (size_t)(256 + h * HS + c) * HWP;

    for (int n0 = 0; n0 < HWP; n0 += NT) {
#pragma unroll
        for (int i = 0; i < 4; i++) {
            int f  = tid + i * 256;
            int r  = f >> 5;
            int c4 = (f & 31) * 4;
            float4 vv = *(const float4*)(vg + (size_t)r * HWP + n0 + c4);
            qs[r][c4 + 0] = vv.x; qs[r][c4 + 1] = vv.y;
            qs[r][c4 + 2] = vv.z; qs[r][c4 + 3] = vv.w;
        }
        __syncthreads();
#pragma unroll
        for (int it = 0; it < NT / 8; it++) {
            int n = it * 8 + ng;
            float s = 0.f;
#pragma unroll
            for (int d = 0; d < 32; d++) s += wreg[d] * qs[d][n];
            og[n0 + n] = s;
        }
        __syncthreads();
    }
}

// ---------------- launcher ----------------
extern "C" void kernel_launch(void* const* d_in, const int* in_sizes, int n_in,
                              void* d_out, int out_size) {
    const float* x        = (const float*)d_in[0];
    const float* mod_mult = (const float*)d_in[1];
    const float* mod_bias = (const float*)d_in[2];
    const float* qkv_w    = (const float*)d_in[3];
    const float* qkv_b    = (const float*)d_in[4];
    const float* pe_q_h   = (const float*)d_in[5];
    const float* pe_q_w   = (const float*)d_in[6];
    const float* pe_k_h   = (const float*)d_in[7];
    const float* pe_k_w   = (const float*)d_in[8];
    const float* pab      = (const float*)d_in[9];
    const float* pqb      = (const float*)d_in[10];
    float* out = (float*)d_out;

    __nv_bfloat16 *xh, *xl, *wh, *wl;
    float *biasH, *peW, *qkv;
    cudaGetSymbolAddress((void**)&xh, g_xh);
    cudaGetSymbolAddress((void**)&xl, g_xl);
    cudaGetSymbolAddress((void**)&wh, g_wh);
    cudaGetSymbolAddress((void**)&wl, g_wl);
    cudaGetSymbolAddress((void**)&biasH, g_biasH);
    cudaGetSymbolAddress((void**)&peW, g_peW);
    cudaGetSymbolAddress((void**)&qkv, g_qkv);

    cudaFuncSetAttribute(qkv_gemm_mma, cudaFuncAttributeMaxDynamicSharedMemorySize, GSMEM);

    // 1) silu -> out[:,0:256] + bf16 splits transposed
    silu_split_kernel<<<4096, 256>>>(x, pab, out, xh, xl);
    // 2) prep: W split, bias/PE fold
    prep_kernel<<<CO, 64>>>(qkv_w, qkv_b, pqb, pe_q_h, pe_q_w, pe_k_h, pe_k_w,
                            wh, wl, biasH, peW);
    // 3) tensor-core QKV GEMM + epilogue -> g_qkv
    dim3 g3(HWP / 128, CO / 128, B_);   // (32, 6, 16)
    qkv_gemm_mma<<<g3, 256, GSMEM>>>(xh, xl, wh, wl, biasH, peW,
                                     mod_mult, mod_bias, qkv);
    // 4) channel attention -> out[:,256:512]
    attn_kernel<<<B_ * NH, 256>>>(out);
}

// round 4
// speedup vs baseline: 1.6289x; 1.1268x over previous
#include <cuda_runtime.h>
#include <cuda_bf16.h>
#include <math.h>
#include <stdint.h>

#define B_   16
#define C_   256
#define HWP  4096
#define CO   768
#define NH   8
#define HS   32

// scratch
__device__ float          g_qkv[(size_t)B_ * CO * HWP];
__device__ __nv_bfloat16  g_xh[(size_t)B_ * HWP * C_];
__device__ __nv_bfloat16  g_xl[(size_t)B_ * HWP * C_];
__device__ __nv_bfloat16  g_wh[(size_t)CO * C_];
__device__ __nv_bfloat16  g_wl[(size_t)CO * C_];
__device__ float          g_biasH[(size_t)CO * 64];
__device__ float          g_peW[(size_t)CO * 64];
__device__ float          g_lp[(size_t)B_ * NH * 8 * 1024];   // logit partials
__device__ float          g_wts[(size_t)B_ * NH * 1024];      // softmax weights

__device__ __forceinline__ uint32_t smem_u32(const void* p) {
    uint32_t a;
    asm("{ .reg .u64 t; cvta.to.shared.u64 t, %1; cvt.u32.u64 %0, t; }" : "=r"(a) : "l"(p));
    return a;
}
__device__ __forceinline__ void ldsm_x4(uint32_t* r, uint32_t addr) {
    asm volatile("ldmatrix.sync.aligned.m8n8.x4.shared.b16 {%0,%1,%2,%3}, [%4];"
        : "=r"(r[0]), "=r"(r[1]), "=r"(r[2]), "=r"(r[3]) : "r"(addr));
}
__device__ __forceinline__ void mma_bf16(float* c, const uint32_t* a, const uint32_t* b) {
    asm volatile("mma.sync.aligned.m16n8k16.row.col.f32.bf16.bf16.f32 "
        "{%0,%1,%2,%3}, {%4,%5,%6,%7}, {%8,%9}, {%0,%1,%2,%3};"
        : "+f"(c[0]), "+f"(c[1]), "+f"(c[2]), "+f"(c[3])
        : "r"(a[0]), "r"(a[1]), "r"(a[2]), "r"(a[3]), "r"(b[0]), "r"(b[1]));
}
// packed f32x2
typedef unsigned long long ull;
__device__ __forceinline__ ull pack2(float lo, float hi) {
    ull r; asm("mov.b64 %0, {%1, %2};" : "=l"(r) : "f"(lo), "f"(hi)); return r;
}
__device__ __forceinline__ void unpack2(ull v, float& lo, float& hi) {
    asm("mov.b64 {%0, %1}, %2;" : "=f"(lo), "=f"(hi) : "l"(v));
}
__device__ __forceinline__ ull ffma2(ull a, ull b, ull c) {
    ull d; asm("fma.rn.f32x2 %0, %1, %2, %3;" : "=l"(d) : "l"(a), "l"(b), "l"(c)); return d;
}
__device__ __forceinline__ float silu_f(float v) { return v / (1.0f + expf(-v)); }

// ---------------- Kernel 1: silu + bf16 hi/lo transpose ----------------
__global__ __launch_bounds__(256)
void silu_split_kernel(const float* __restrict__ x, const float* __restrict__ pab,
                       float* __restrict__ out,
                       __nv_bfloat16* __restrict__ xh, __nv_bfloat16* __restrict__ xl) {
    __shared__ float s[64][65];
    const int bid = blockIdx.x;
    const int p0 = (bid & 63) * 64;
    const int c0 = ((bid >> 6) & 3) * 64;
    const int b  = bid >> 8;
    const int tid = threadIdx.x;
#pragma unroll
    for (int ii = 0; ii < 4; ii++) {
        int lin = tid + ii * 256;
        int r = lin >> 4, u = lin & 15;
        float4 v = *(const float4*)(x + (size_t)(b * 256 + c0 + r) * HWP + p0 + u * 4);
        float pb = pab[c0 + r];
        float4 o;
        o.x = silu_f(v.x + pb); o.y = silu_f(v.y + pb);
        o.z = silu_f(v.z + pb); o.w = silu_f(v.w + pb);
        *(float4*)(out + (size_t)(b * 512 + c0 + r) * HWP + p0 + u * 4) = o;
        s[r][u * 4 + 0] = o.x; s[r][u * 4 + 1] = o.y;
        s[r][u * 4 + 2] = o.z; s[r][u * 4 + 3] = o.w;
    }
    __syncthreads();
#pragma unroll
    for (int ii = 0; ii < 4; ii++) {
        int lin = tid + ii * 256;
        int r = lin >> 4, u = lin & 15;
        float v[4];
#pragma unroll
        for (int j = 0; j < 4; j++) v[j] = s[u * 4 + j][r];
        __nv_bfloat16 h[4], l[4];
#pragma unroll
        for (int j = 0; j < 4; j++) {
            h[j] = __float2bfloat16(v[j]);
            l[j] = __float2bfloat16(v[j] - __bfloat162float(h[j]));
        }
        size_t base = (size_t)(b * HWP + p0 + r) * C_ + c0 + u * 4;
        __nv_bfloat162 hh0 = {h[0], h[1]}, hh1 = {h[2], h[3]};
        __nv_bfloat162 ll0 = {l[0], l[1]}, ll1 = {l[2], l[3]};
        *(uint2*)(xh + base) = make_uint2(*(uint32_t*)&hh0, *(uint32_t*)&hh1);
        *(uint2*)(xl + base) = make_uint2(*(uint32_t*)&ll0, *(uint32_t*)&ll1);
    }
}

// ---------------- Kernel 2: prep ----------------
__global__ __launch_bounds__(64)
void prep_kernel(const float* __restrict__ W, const float* __restrict__ qkv_b,
                 const float* __restrict__ pqb,
                 const float* __restrict__ peqh, const float* __restrict__ peqw,
                 const float* __restrict__ pekh, const float* __restrict__ pekw,
                 __nv_bfloat16* __restrict__ wh, __nv_bfloat16* __restrict__ wl,
                 float* __restrict__ biasH, float* __restrict__ peW) {
    const int o = blockIdx.x;
    const int t = threadIdx.x;
    __shared__ float red[2];
    float part = 0.f;
#pragma unroll
    for (int j = 0; j < 4; j++) {
        int c = t * 4 + j;
        float w = W[(size_t)o * C_ + c];
        __nv_bfloat16 h = __float2bfloat16(w);
        __nv_bfloat16 l = __float2bfloat16(w - __bfloat162float(h));
        wh[(size_t)o * C_ + c] = h;
        wl[(size_t)o * C_ + c] = l;
        part += w * pqb[c];
    }
#pragma unroll
    for (int off = 16; off > 0; off >>= 1) part += __shfl_xor_sync(0xffffffffu, part, off);
    if ((t & 31) == 0) red[t >> 5] = part;
    __syncthreads();
    float base = qkv_b[o] + red[0] + red[1];
    int y = t;
    float bh, pw;
    if (o < 256)      { bh = base + peqh[o * 64 + y];          pw = peqw[o * 64 + y]; }
    else if (o < 512) { int c = o - 256; bh = base + pekh[c * 64 + y]; pw = pekw[c * 64 + y]; }
    else              { bh = base; pw = 0.f; }
    biasH[o * 64 + y] = bh;
    peW[o * 64 + y]   = pw;
}

// ---------------- Kernel 3: mma.sync bf16 split GEMM, cp.async double-buffered ----------------
#define KC       64
#define TILE_BYT (128 * 144)                // 18432 B per tile (rows of 144B)
#define STAGE_BYT (4 * TILE_BYT)            // 73728
#define GSMEM    (2 * STAGE_BYT)            // 147456

__device__ __forceinline__ void load_tile_async(uint32_t sm, const __nv_bfloat16* g, int tid) {
#pragma unroll
    for (int ii = 0; ii < 4; ii++) {
        int lin = tid + ii * 256;
        int r = lin >> 3, u = lin & 7;
        uint32_t dst = sm + r * 144 + u * 16;
        const __nv_bfloat16* src = g + (size_t)r * C_ + u * 8;
        asm volatile("cp.async.cg.shared.global [%0], [%1], 16;" :: "r"(dst), "l"(src));
    }
}

__global__ __launch_bounds__(256, 1)
void qkv_gemm_mma(const __nv_bfloat16* __restrict__ xh, const __nv_bfloat16* __restrict__ xl,
                  const __nv_bfloat16* __restrict__ wh, const __nv_bfloat16* __restrict__ wl,
                  const float* __restrict__ biasH, const float* __restrict__ peW,
                  const float* __restrict__ mod_mult, const float* __restrict__ mod_bias,
                  float* __restrict__ qkv) {
    extern __shared__ __align__(16) char dyn[];
    const uint32_t ubase = smem_u32(dyn);

    const int p0 = blockIdx.x * 128;
    const int o0 = blockIdx.y * 128;
    const int b  = blockIdx.z;
    const int tid = threadIdx.x, wid = tid >> 5, lane = tid & 31;
    const int warp_m = (wid & 1) * 64;
    const int warp_n = (wid >> 1) * 32;

    float c[4][4][4];
#pragma unroll
    for (int i = 0; i < 4; i++)
#pragma unroll
        for (int j = 0; j < 4; j++)
#pragma unroll
            for (int q = 0; q < 4; q++) c[i][j][q] = 0.f;

    const uint32_t a_lrow = (uint32_t)(lane & 15) * 144 + (uint32_t)(lane >> 4) * 16;
    const uint32_t b_lrow = (uint32_t)(((lane >> 4) << 3) + (lane & 7)) * 144
                          + (uint32_t)((lane >> 3) & 1) * 16;

    const __nv_bfloat16* gAh = wh + (size_t)o0 * C_;
    const __nv_bfloat16* gAl = wl + (size_t)o0 * C_;
    const __nv_bfloat16* gBh = xh + (size_t)(b * HWP + p0) * C_;
    const __nv_bfloat16* gBl = xl + (size_t)(b * HWP + p0) * C_;

    // prefetch chunk 0 into stage 0
    load_tile_async(ubase + 0 * TILE_BYT, gAh, tid);
    load_tile_async(ubase + 1 * TILE_BYT, gAl, tid);
    load_tile_async(ubase + 2 * TILE_BYT, gBh, tid);
    load_tile_async(ubase + 3 * TILE_BYT, gBl, tid);
    asm volatile("cp.async.commit_group;");

    for (int ch = 0; ch < 4; ch++) {
        const int st = ch & 1;
        if (ch < 3) {
            uint32_t sb = ubase + (1 - st) * STAGE_BYT;
            load_tile_async(sb + 0 * TILE_BYT, gAh + (ch + 1) * KC, tid);
            load_tile_async(sb + 1 * TILE_BYT, gAl + (ch + 1) * KC, tid);
            load_tile_async(sb + 2 * TILE_BYT, gBh + (ch + 1) * KC, tid);
            load_tile_async(sb + 3 * TILE_BYT, gBl + (ch + 1) * KC, tid);
            asm volatile("cp.async.commit_group;");
            asm volatile("cp.async.wait_group 1;");
        } else {
            asm volatile("cp.async.wait_group 0;");
        }
        __syncthreads();

        const uint32_t uAh = ubase + st * STAGE_BYT;
        const uint32_t uAl = uAh + TILE_BYT;
        const uint32_t uBh = uAh + 2 * TILE_BYT;
        const uint32_t uBl = uAh + 3 * TILE_BYT;
#pragma unroll
        for (int ks = 0; ks < 4; ks++) {
            uint32_t ah[4][4], al[4][4], bh[4][2], bl[4][2];
#pragma unroll
            for (int mt = 0; mt < 4; mt++) {
                uint32_t ra = (uint32_t)(warp_m + mt * 16) * 144 + ks * 32;
                ldsm_x4(ah[mt], uAh + ra + a_lrow);
                ldsm_x4(al[mt], uAl + ra + a_lrow);
            }
#pragma unroll
            for (int nt2 = 0; nt2 < 2; nt2++) {
                uint32_t rb = (uint32_t)(warp_n + nt2 * 16) * 144 + ks * 32;
                uint32_t t0[4], t1[4];
                ldsm_x4(t0, uBh + rb + b_lrow);
                ldsm_x4(t1, uBl + rb + b_lrow);
                bh[nt2 * 2][0] = t0[0]; bh[nt2 * 2][1] = t0[1];
                bh[nt2 * 2 + 1][0] = t0[2]; bh[nt2 * 2 + 1][1] = t0[3];
                bl[nt2 * 2][0] = t1[0]; bl[nt2 * 2][1] = t1[1];
                bl[nt2 * 2 + 1][0] = t1[2]; bl[nt2 * 2 + 1][1] = t1[3];
            }
#pragma unroll
            for (int mt = 0; mt < 4; mt++)
#pragma unroll
                for (int nt = 0; nt < 4; nt++) {
                    mma_bf16(c[mt][nt], ah[mt], bh[nt]);
                    mma_bf16(c[mt][nt], ah[mt], bl[nt]);
                    mma_bf16(c[mt][nt], al[mt], bh[nt]);
                }
        }
        __syncthreads();
    }

    const int g  = lane >> 2;
    const int t  = lane & 3;
    const bool isQ = (o0 < 256);
#pragma unroll
    for (int mt = 0; mt < 4; mt++) {
#pragma unroll
        for (int nt = 0; nt < 4; nt++) {
            int p  = p0 + warp_n + nt * 8 + 2 * t;
            int y  = p >> 6;
            int xw = p & 63;
#pragma unroll
            for (int half = 0; half < 2; half++) {
                int o = o0 + warp_m + mt * 16 + g + half * 8;
                float bias = biasH[o * 64 + y];
                float v0 = c[mt][nt][half * 2 + 0] + bias + peW[o * 64 + xw];
                float v1 = c[mt][nt][half * 2 + 1] + bias + peW[o * 64 + xw + 1];
                if (isQ) {
                    float mm = mod_mult[b * 256 + o];
                    float mb = mod_bias[b * 256 + o];
                    v0 = fmaf(v0, mm, mb);
                    v1 = fmaf(v1, mm, mb);
                }
                *(float2*)(qkv + ((size_t)b * CO + o) * HWP + p) = make_float2(v0, v1);
            }
        }
    }
}

// ---------------- Kernel 4a: partial logits (n-split x8, f32x2) ----------------
#define SROWF 134    // smem row stride in floats (conflict-free for 16-way d access)

__global__ __launch_bounds__(256)
void attn_logits(const float* __restrict__ qkv, float* __restrict__ lp) {
    __shared__ float qs[32][SROWF];
    __shared__ float ks[32][SROWF];
    const int s = blockIdx.x, h = blockIdx.y, b = blockIdx.z;
    const float* qg = qkv + ((size_t)b * CO + h * HS) * HWP + s * 512;
    const float* kg = qg + (size_t)256 * HWP;
    const int tid = threadIdx.x;
    const int c0 = (tid >> 4) * 2, d0 = (tid & 15) * 2;

    ull A00 = pack2(0.f, 0.f), A01 = A00, A10 = A00, A11 = A00;

    for (int t = 0; t < 4; t++) {
#pragma unroll
        for (int i = 0; i < 4; i++) {
            int lin = tid + i * 256;
            int r = lin >> 5, c4 = (lin & 31) * 4;
            float4 qv = *(const float4*)(qg + (size_t)r * HWP + t * 128 + c4);
            qs[r][c4 + 0] = qv.x; qs[r][c4 + 1] = qv.y;
            qs[r][c4 + 2] = qv.z; qs[r][c4 + 3] = qv.w;
            float4 kv = *(const float4*)(kg + (size_t)r * HWP + t * 128 + c4);
            ks[r][c4 + 0] = kv.x; ks[r][c4 + 1] = kv.y;
            ks[r][c4 + 2] = kv.z; ks[r][c4 + 3] = kv.w;
        }
        __syncthreads();
#pragma unroll 8
        for (int i = 0; i < 64; i++) {
            ull q0 = *(const ull*)&qs[c0][2 * i];
            ull q1 = *(const ull*)&qs[c0 + 1][2 * i];
            ull k0 = *(const ull*)&ks[d0][2 * i];
            ull k1 = *(const ull*)&ks[d0 + 1][2 * i];
            A00 = ffma2(q0, k0, A00); A01 = ffma2(q0, k1, A01);
            A10 = ffma2(q1, k0, A10); A11 = ffma2(q1, k1, A11);
        }
        __syncthreads();
    }
    float x0, x1, a00, a01, a10, a11;
    unpack2(A00, x0, x1); a00 = x0 + x1;
    unpack2(A01, x0, x1); a01 = x0 + x1;
    unpack2(A10, x0, x1); a10 = x0 + x1;
    unpack2(A11, x0, x1); a11 = x0 + x1;
    float* dst = lp + (((size_t)(b * NH + h) * 8 + s) * 1024);
    *(float2*)&dst[c0 * 32 + d0]       = make_float2(a00, a01);
    *(float2*)&dst[(c0 + 1) * 32 + d0] = make_float2(a10, a11);
}

// ---------------- Kernel 4b: reduce partials + softmax ----------------
__global__ __launch_bounds__(1024)
void attn_softmax(const float* __restrict__ lp, float* __restrict__ wts) {
    const int bh = blockIdx.x;
    const int tid = threadIdx.x;
    const int c = tid >> 5, d = tid & 31;
    size_t base = (size_t)bh * 8 * 1024 + c * 32 + d;
    float v = 0.f;
#pragma unroll
    for (int s = 0; s < 8; s++) v += lp[base + s * 1024];
    v *= 0.17677669529663687f;    // 1/sqrt(32)
    float mx = v;
#pragma unroll
    for (int o = 16; o > 0; o >>= 1) mx = fmaxf(mx, __shfl_xor_sync(0xffffffffu, mx, o));
    float e = expf(v - mx);
    float sm = e;
#pragma unroll
    for (int o = 16; o > 0; o >>= 1) sm += __shfl_xor_sync(0xffffffffu, sm, o);
    wts[(size_t)bh * 1024 + c * 32 + d] = e / sm;
}

// ---------------- Kernel 4c: out = W·V (n-split x8, f32x2) ----------------
__global__ __launch_bounds__(256)
void attn_out(const float* __restrict__ qkv, const float* __restrict__ wts,
              float* __restrict__ out) {
    __shared__ float vs[32][SROWF];
    __shared__ float ws[32][32];
    const int s = blockIdx.x, h = blockIdx.y, b = blockIdx.z;
    const int bh = b * NH + h;
    const float* vg = qkv + ((size_t)b * CO + 512 + h * HS) * HWP + s * 512;
    float* og = out + ((size_t)b * 512 + 256 + h * HS) * HWP + s * 512;
    const int tid = threadIdx.x;

    *(float4*)&((float*)ws)[tid * 4] = *(const float4*)(wts + (size_t)bh * 1024 + tid * 4);
    __syncthreads();

    const int cc = tid >> 3, ng = tid & 7;
    ull wp[32];
#pragma unroll
    for (int d = 0; d < 32; d++) { float w = ws[cc][d]; wp[d] = pack2(w, w); }

    for (int t = 0; t < 4; t++) {
#pragma unroll
        for (int i = 0; i < 4; i++) {
            int lin = tid + i * 256;
            int r = lin >> 5, c4 = (lin & 31) * 4;
            float4 vv = *(const float4*)(vg + (size_t)r * HWP + t * 128 + c4);
            vs[r][c4 + 0] = vv.x; vs[r][c4 + 1] = vv.y;
            vs[r][c4 + 2] = vv.z; vs[r][c4 + 3] = vv.w;
        }
        __syncthreads();
#pragma unroll
        for (int i = 0; i < 8; i++) {
            int np = (ng + 8 * i) * 2;
            ull acc = pack2(0.f, 0.f);
#pragma unroll
            for (int d = 0; d < 32; d++) acc = ffma2(wp[d], *(const ull*)&vs[d][np], acc);
            float v0, v1; unpack2(acc, v0, v1);
            *(float2*)(og + (size_t)cc * HWP + t * 128 + np) = make_float2(v0, v1);
        }
        __syncthreads();
    }
}

// ---------------- launcher ----------------
extern "C" void kernel_launch(void* const* d_in, const int* in_sizes, int n_in,
                              void* d_out, int out_size) {
    const float* x        = (const float*)d_in[0];
    const float* mod_mult = (const float*)d_in[1];
    const float* mod_bias = (const float*)d_in[2];
    const float* qkv_w    = (const float*)d_in[3];
    const float* qkv_b    = (const float*)d_in[4];
    const float* pe_q_h   = (const float*)d_in[5];
    const float* pe_q_w   = (const float*)d_in[6];
    const float* pe_k_h   = (const float*)d_in[7];
    const float* pe_k_w   = (const float*)d_in[8];
    const float* pab      = (const float*)d_in[9];
    const float* pqb      = (const float*)d_in[10];
    float* out = (float*)d_out;

    __nv_bfloat16 *xh, *xl, *wh, *wl;
    float *biasH, *peW, *qkv, *lp, *wts;
    cudaGetSymbolAddress((void**)&xh, g_xh);
    cudaGetSymbolAddress((void**)&xl, g_xl);
    cudaGetSymbolAddress((void**)&wh, g_wh);
    cudaGetSymbolAddress((void**)&wl, g_wl);
    cudaGetSymbolAddress((void**)&biasH, g_biasH);
    cudaGetSymbolAddress((void**)&peW, g_peW);
    cudaGetSymbolAddress((void**)&qkv, g_qkv);
    cudaGetSymbolAddress((void**)&lp, g_lp);
    cudaGetSymbolAddress((void**)&wts, g_wts);

    cudaFuncSetAttribute(qkv_gemm_mma, cudaFuncAttributeMaxDynamicSharedMemorySize, GSMEM);

    silu_split_kernel<<<4096, 256>>>(x, pab, out, xh, xl);
    prep_kernel<<<CO, 64>>>(qkv_w, qkv_b, pqb, pe_q_h, pe_q_w, pe_k_h, pe_k_w,
                            wh, wl, biasH, peW);
    dim3 g3(HWP / 128, CO / 128, B_);
    qkv_gemm_mma<<<g3, 256, GSMEM>>>(xh, xl, wh, wl, biasH, peW,
                                     mod_mult, mod_bias, qkv);
    dim3 ga(8, NH, B_);
    attn_logits<<<ga, 256>>>(qkv, lp);
    attn_softmax<<<B_ * NH, 1024>>>(lp, wts);
    attn_out<<<ga, 256>>>(qkv, wts, out);
}

// round 5
// speedup vs baseline: 1.9178x; 1.1774x over previous
#include <cuda_runtime.h>
#include <cuda_bf16.h>
#include <math.h>
#include <stdint.h>

#define B_   16
#define C_   256
#define HWP  4096
#define CO   768
#define NH   8
#define HS   32

// scratch
__device__ float          g_qkv[(size_t)B_ * CO * HWP];
__device__ __nv_bfloat16  g_xh[(size_t)B_ * HWP * C_];
__device__ __nv_bfloat16  g_xl[(size_t)B_ * HWP * C_];
__device__ __nv_bfloat16  g_wh[(size_t)CO * C_];
__device__ __nv_bfloat16  g_wl[(size_t)CO * C_];
__device__ float          g_biasH[(size_t)CO * 64];
__device__ float          g_peW[(size_t)CO * 64];
__device__ float          g_lp[(size_t)B_ * NH * 32 * 1024];  // 32 logit partials
__device__ float          g_wts[(size_t)B_ * NH * 1024];

__device__ __forceinline__ uint32_t smem_u32(const void* p) {
    uint32_t a;
    asm("{ .reg .u64 t; cvta.to.shared.u64 t, %1; cvt.u32.u64 %0, t; }" : "=r"(a) : "l"(p));
    return a;
}
__device__ __forceinline__ void ldsm_x4(uint32_t* r, uint32_t addr) {
    asm volatile("ldmatrix.sync.aligned.m8n8.x4.shared.b16 {%0,%1,%2,%3}, [%4];"
        : "=r"(r[0]), "=r"(r[1]), "=r"(r[2]), "=r"(r[3]) : "r"(addr));
}
__device__ __forceinline__ void mma_bf16(float* c, const uint32_t* a, const uint32_t* b) {
    asm volatile("mma.sync.aligned.m16n8k16.row.col.f32.bf16.bf16.f32 "
        "{%0,%1,%2,%3}, {%4,%5,%6,%7}, {%8,%9}, {%0,%1,%2,%3};"
        : "+f"(c[0]), "+f"(c[1]), "+f"(c[2]), "+f"(c[3])
        : "r"(a[0]), "r"(a[1]), "r"(a[2]), "r"(a[3]), "r"(b[0]), "r"(b[1]));
}
typedef unsigned long long ull;
__device__ __forceinline__ ull pack2(float lo, float hi) {
    ull r; asm("mov.b64 %0, {%1, %2};" : "=l"(r) : "f"(lo), "f"(hi)); return r;
}
__device__ __forceinline__ void unpack2(ull v, float& lo, float& hi) {
    asm("mov.b64 {%0, %1}, %2;" : "=f"(lo), "=f"(hi) : "l"(v));
}
__device__ __forceinline__ ull ffma2(ull a, ull b, ull c) {
    ull d; asm("fma.rn.f32x2 %0, %1, %2, %3;" : "=l"(d) : "l"(a), "l"(b), "l"(c)); return d;
}
__device__ __forceinline__ float silu_f(float v) { return v / (1.0f + expf(-v)); }

// ---------------- Kernel 1: silu + bf16 hi/lo transpose ----------------
__global__ __launch_bounds__(256)
void silu_split_kernel(const float* __restrict__ x, const float* __restrict__ pab,
                       float* __restrict__ out,
                       __nv_bfloat16* __restrict__ xh, __nv_bfloat16* __restrict__ xl) {
    __shared__ float s[64][65];
    const int bid = blockIdx.x;
    const int p0 = (bid & 63) * 64;
    const int c0 = ((bid >> 6) & 3) * 64;
    const int b  = bid >> 8;
    const int tid = threadIdx.x;
#pragma unroll
    for (int ii = 0; ii < 4; ii++) {
        int lin = tid + ii * 256;
        int r = lin >> 4, u = lin & 15;
        float4 v = *(const float4*)(x + (size_t)(b * 256 + c0 + r) * HWP + p0 + u * 4);
        float pb = pab[c0 + r];
        float4 o;
        o.x = silu_f(v.x + pb); o.y = silu_f(v.y + pb);
        o.z = silu_f(v.z + pb); o.w = silu_f(v.w + pb);
        *(float4*)(out + (size_t)(b * 512 + c0 + r) * HWP + p0 + u * 4) = o;
        s[r][u * 4 + 0] = o.x; s[r][u * 4 + 1] = o.y;
        s[r][u * 4 + 2] = o.z; s[r][u * 4 + 3] = o.w;
    }
    __syncthreads();
#pragma unroll
    for (int ii = 0; ii < 4; ii++) {
        int lin = tid + ii * 256;
        int r = lin >> 4, u = lin & 15;
        float v[4];
#pragma unroll
        for (int j = 0; j < 4; j++) v[j] = s[u * 4 + j][r];
        __nv_bfloat16 h[4], l[4];
#pragma unroll
        for (int j = 0; j < 4; j++) {
            h[j] = __float2bfloat16(v[j]);
            l[j] = __float2bfloat16(v[j] - __bfloat162float(h[j]));
        }
        size_t base = (size_t)(b * HWP + p0 + r) * C_ + c0 + u * 4;
        __nv_bfloat162 hh0 = {h[0], h[1]}, hh1 = {h[2], h[3]};
        __nv_bfloat162 ll0 = {l[0], l[1]}, ll1 = {l[2], l[3]};
        *(uint2*)(xh + base) = make_uint2(*(uint32_t*)&hh0, *(uint32_t*)&hh1);
        *(uint2*)(xl + base) = make_uint2(*(uint32_t*)&ll0, *(uint32_t*)&ll1);
    }
}

// ---------------- Kernel 2: prep ----------------
__global__ __launch_bounds__(64)
void prep_kernel(const float* __restrict__ W, const float* __restrict__ qkv_b,
                 const float* __restrict__ pqb,
                 const float* __restrict__ peqh, const float* __restrict__ peqw,
                 const float* __restrict__ pekh, const float* __restrict__ pekw,
                 __nv_bfloat16* __restrict__ wh, __nv_bfloat16* __restrict__ wl,
                 float* __restrict__ biasH, float* __restrict__ peW) {
    const int o = blockIdx.x;
    const int t = threadIdx.x;
    __shared__ float red[2];
    float part = 0.f;
#pragma unroll
    for (int j = 0; j < 4; j++) {
        int c = t * 4 + j;
        float w = W[(size_t)o * C_ + c];
        __nv_bfloat16 h = __float2bfloat16(w);
        __nv_bfloat16 l = __float2bfloat16(w - __bfloat162float(h));
        wh[(size_t)o * C_ + c] = h;
        wl[(size_t)o * C_ + c] = l;
        part += w * pqb[c];
    }
#pragma unroll
    for (int off = 16; off > 0; off >>= 1) part += __shfl_xor_sync(0xffffffffu, part, off);
    if ((t & 31) == 0) red[t >> 5] = part;
    __syncthreads();
    float base = qkv_b[o] + red[0] + red[1];
    int y = t;
    float bh, pw;
    if (o < 256)      { bh = base + peqh[o * 64 + y];          pw = peqw[o * 64 + y]; }
    else if (o < 512) { int c = o - 256; bh = base + pekh[c * 64 + y]; pw = pekw[c * 64 + y]; }
    else              { bh = base; pw = 0.f; }
    biasH[o * 64 + y] = bh;
    peW[o * 64 + y]   = pw;
}

// ---------------- Kernel 3: mma.sync split GEMM, KC=32, 2 CTA/SM ----------------
#define KC        32
#define TROW      80                        // 32 bf16 = 64B + 16B pad
#define TILE_BYT  (128 * TROW)              // 10240
#define STAGE_BYT (4 * TILE_BYT)            // 40960
#define GSMEM     (2 * STAGE_BYT)           // 81920

__device__ __forceinline__ void load_tile_async(uint32_t sm, const __nv_bfloat16* g, int tid) {
#pragma unroll
    for (int ii = 0; ii < 2; ii++) {
        int lin = tid + ii * 256;            // 0..511
        int r = lin >> 2, u = lin & 3;
        uint32_t dst = sm + r * TROW + u * 16;
        const __nv_bfloat16* src = g + (size_t)r * C_ + u * 8;
        asm volatile("cp.async.cg.shared.global [%0], [%1], 16;" :: "r"(dst), "l"(src));
    }
}

__global__ __launch_bounds__(256, 2)
void qkv_gemm_mma(const __nv_bfloat16* __restrict__ xh, const __nv_bfloat16* __restrict__ xl,
                  const __nv_bfloat16* __restrict__ wh, const __nv_bfloat16* __restrict__ wl,
                  const float* __restrict__ biasH, const float* __restrict__ peW,
                  const float* __restrict__ mod_mult, const float* __restrict__ mod_bias,
                  float* __restrict__ qkv) {
    extern __shared__ __align__(16) char dyn[];
    const uint32_t ubase = smem_u32(dyn);

    const int p0 = blockIdx.x * 128;
    const int o0 = blockIdx.y * 128;
    const int b  = blockIdx.z;
    const int tid = threadIdx.x, wid = tid >> 5, lane = tid & 31;
    const int warp_m = (wid & 1) * 64;
    const int warp_n = (wid >> 1) * 32;

    float c[4][4][4];
#pragma unroll
    for (int i = 0; i < 4; i++)
#pragma unroll
        for (int j = 0; j < 4; j++)
#pragma unroll
            for (int q = 0; q < 4; q++) c[i][j][q] = 0.f;

    const uint32_t a_lrow = (uint32_t)(lane & 15) * TROW + (uint32_t)(lane >> 4) * 16;
    const uint32_t b_lrow = (uint32_t)(((lane >> 4) << 3) + (lane & 7)) * TROW
                          + (uint32_t)((lane >> 3) & 1) * 16;

    const __nv_bfloat16* gAh = wh + (size_t)o0 * C_;
    const __nv_bfloat16* gAl = wl + (size_t)o0 * C_;
    const __nv_bfloat16* gBh = xh + (size_t)(b * HWP + p0) * C_;
    const __nv_bfloat16* gBl = xl + (size_t)(b * HWP + p0) * C_;

    load_tile_async(ubase + 0 * TILE_BYT, gAh, tid);
    load_tile_async(ubase + 1 * TILE_BYT, gAl, tid);
    load_tile_async(ubase + 2 * TILE_BYT, gBh, tid);
    load_tile_async(ubase + 3 * TILE_BYT, gBl, tid);
    asm volatile("cp.async.commit_group;");

    for (int ch = 0; ch < 8; ch++) {
        const int st = ch & 1;
        if (ch < 7) {
            uint32_t sb = ubase + (1 - st) * STAGE_BYT;
            load_tile_async(sb + 0 * TILE_BYT, gAh + (ch + 1) * KC, tid);
            load_tile_async(sb + 1 * TILE_BYT, gAl + (ch + 1) * KC, tid);
            load_tile_async(sb + 2 * TILE_BYT, gBh + (ch + 1) * KC, tid);
            load_tile_async(sb + 3 * TILE_BYT, gBl + (ch + 1) * KC, tid);
            asm volatile("cp.async.commit_group;");
            asm volatile("cp.async.wait_group 1;");
        } else {
            asm volatile("cp.async.wait_group 0;");
        }
        __syncthreads();

        const uint32_t uAh = ubase + st * STAGE_BYT;
        const uint32_t uAl = uAh + TILE_BYT;
        const uint32_t uBh = uAh + 2 * TILE_BYT;
        const uint32_t uBl = uAh + 3 * TILE_BYT;
#pragma unroll
        for (int ks = 0; ks < 2; ks++) {
            uint32_t ah[4][4], al[4][4], bh[4][2], bl[4][2];
#pragma unroll
            for (int mt = 0; mt < 4; mt++) {
                uint32_t ra = (uint32_t)(warp_m + mt * 16) * TROW + ks * 32;
                ldsm_x4(ah[mt], uAh + ra + a_lrow);
                ldsm_x4(al[mt], uAl + ra + a_lrow);
            }
#pragma unroll
            for (int nt2 = 0; nt2 < 2; nt2++) {
                uint32_t rb = (uint32_t)(warp_n + nt2 * 16) * TROW + ks * 32;
                uint32_t t0[4], t1[4];
                ldsm_x4(t0, uBh + rb + b_lrow);
                ldsm_x4(t1, uBl + rb + b_lrow);
                bh[nt2 * 2][0] = t0[0]; bh[nt2 * 2][1] = t0[1];
                bh[nt2 * 2 + 1][0] = t0[2]; bh[nt2 * 2 + 1][1] = t0[3];
                bl[nt2 * 2][0] = t1[0]; bl[nt2 * 2][1] = t1[1];
                bl[nt2 * 2 + 1][0] = t1[2]; bl[nt2 * 2 + 1][1] = t1[3];
            }
#pragma unroll
            for (int mt = 0; mt < 4; mt++)
#pragma unroll
                for (int nt = 0; nt < 4; nt++) {
                    mma_bf16(c[mt][nt], ah[mt], bh[nt]);
                    mma_bf16(c[mt][nt], ah[mt], bl[nt]);
                    mma_bf16(c[mt][nt], al[mt], bh[nt]);
                }
        }
        __syncthreads();
    }

    const int g  = lane >> 2;
    const int t  = lane & 3;
    const bool isQ = (o0 < 256);
#pragma unroll
    for (int mt = 0; mt < 4; mt++) {
#pragma unroll
        for (int nt = 0; nt < 4; nt++) {
            int p  = p0 + warp_n + nt * 8 + 2 * t;
            int y  = p >> 6;
            int xw = p & 63;
#pragma unroll
            for (int half = 0; half < 2; half++) {
                int o = o0 + warp_m + mt * 16 + g + half * 8;
                float bias = biasH[o * 64 + y];
                float v0 = c[mt][nt][half * 2 + 0] + bias + peW[o * 64 + xw];
                float v1 = c[mt][nt][half * 2 + 1] + bias + peW[o * 64 + xw + 1];
                if (isQ) {
                    float mm = mod_mult[b * 256 + o];
                    float mb = mod_bias[b * 256 + o];
                    v0 = fmaf(v0, mm, mb);
                    v1 = fmaf(v1, mm, mb);
                }
                *(float2*)(qkv + ((size_t)b * CO + o) * HWP + p) = make_float2(v0, v1);
            }
        }
    }
}

// ---------------- shared loader for attention (32 x 128, stride LS) ----------------
#define LS 130
__device__ __forceinline__ void load_chunk(float (*sm)[LS], const float* g, int n0, int tid) {
#pragma unroll
    for (int i = 0; i < 4; i++) {
        int lin = tid + i * 256;
        int r = lin >> 5, c4 = (lin & 31) * 4;
        float4 v = *(const float4*)(g + (size_t)r * HWP + n0 + c4);
        *(float2*)&sm[r][c4]     = make_float2(v.x, v.y);
        *(float2*)&sm[r][c4 + 2] = make_float2(v.z, v.w);
    }
}

// ---------------- Kernel 4a: partial logits (4x4 thread tiles, 4 n-groups) ----------------
__global__ __launch_bounds__(256)
void attn_logits(const float* __restrict__ qkv, float* __restrict__ lp) {
    __shared__ float qs[32][LS];
    __shared__ float ks[32][LS];
    const int s = blockIdx.x, h = blockIdx.y, b = blockIdx.z;
    const float* qg = qkv + ((size_t)b * CO + h * HS) * HWP + s * 512;
    const float* kg = qg + (size_t)256 * HWP;
    const int tid = threadIdx.x;
    const int g   = tid >> 6;
    const int t64 = tid & 63;
    const int cc  = (t64 >> 3) * 4;
    const int dd  = (t64 & 7) * 4;

    ull acc[4][4];
#pragma unroll
    for (int i = 0; i < 4; i++)
#pragma unroll
        for (int j = 0; j < 4; j++) acc[i][j] = pack2(0.f, 0.f);

    for (int t = 0; t < 4; t++) {
        load_chunk(qs, qg, t * 128, tid);
        load_chunk(ks, kg, t * 128, tid);
        __syncthreads();
#pragma unroll 4
        for (int i = 0; i < 16; i++) {
            int nn = g * 32 + 2 * i;
            ull qp[4], kp[4];
#pragma unroll
            for (int j = 0; j < 4; j++) qp[j] = *(const ull*)&qs[cc + j][nn];
#pragma unroll
            for (int j = 0; j < 4; j++) kp[j] = *(const ull*)&ks[dd + j][nn];
#pragma unroll
            for (int a = 0; a < 4; a++)
#pragma unroll
                for (int d = 0; d < 4; d++) acc[a][d] = ffma2(qp[a], kp[d], acc[a][d]);
        }
        __syncthreads();
    }
    float* dst = lp + (((size_t)(b * NH + h) * 8 + s) * 4 + g) * 1024;
#pragma unroll
    for (int a = 0; a < 4; a++) {
        float v[4];
#pragma unroll
        for (int d = 0; d < 4; d++) {
            float x0, x1; unpack2(acc[a][d], x0, x1); v[d] = x0 + x1;
        }
        *(float4*)&dst[(cc + a) * 32 + dd] = make_float4(v[0], v[1], v[2], v[3]);
    }
}

// ---------------- Kernel 4b: reduce 32 partials + softmax ----------------
__global__ __launch_bounds__(1024)
void attn_softmax(const float* __restrict__ lp, float* __restrict__ wts) {
    const int bh = blockIdx.x;
    const int tid = threadIdx.x;
    size_t base = (size_t)bh * 32 * 1024 + tid;
    float v = 0.f;
#pragma unroll
    for (int s = 0; s < 32; s++) v += lp[base + s * 1024];
    v *= 0.17677669529663687f;
    float mx = v;
#pragma unroll
    for (int o = 16; o > 0; o >>= 1) mx = fmaxf(mx, __shfl_xor_sync(0xffffffffu, mx, o));
    float e = expf(v - mx);
    float sm = e;
#pragma unroll
    for (int o = 16; o > 0; o >>= 1) sm += __shfl_xor_sync(0xffffffffu, sm, o);
    wts[(size_t)bh * 1024 + tid] = e / sm;
}

// ---------------- Kernel 4c: out = W·V (d-loop, W transposed in smem) ----------------
__global__ __launch_bounds__(256)
void attn_out(const float* __restrict__ qkv, const float* __restrict__ wts,
              float* __restrict__ out) {
    __shared__ float vs[32][LS];
    __shared__ float wsT[32][36];
    const int s = blockIdx.x, h = blockIdx.y, b = blockIdx.z;
    const int bh = b * NH + h;
    const float* vg = qkv + ((size_t)b * CO + 512 + h * HS) * HWP + s * 512;
    float* og = out + ((size_t)b * 512 + 256 + h * HS) * HWP + s * 512;
    const int tid = threadIdx.x;

    {
        float4 w = *(const float4*)(wts + (size_t)bh * 1024 + tid * 4);
        int c = tid >> 3, d0 = (tid & 7) * 4;
        wsT[d0 + 0][c] = w.x; wsT[d0 + 1][c] = w.y;
        wsT[d0 + 2][c] = w.z; wsT[d0 + 3][c] = w.w;
    }
    __syncthreads();

    const int cc = (tid >> 5) * 4;
    const int nn = (tid & 31) * 4;

    for (int t = 0; t < 4; t++) {
        load_chunk(vs, vg, t * 128, tid);
        __syncthreads();
        ull acc[4][2];
#pragma unroll
        for (int j = 0; j < 4; j++) { acc[j][0] = pack2(0.f, 0.f); acc[j][1] = acc[j][0]; }
#pragma unroll 4
        for (int d = 0; d < 32; d++) {
            float4 w4 = *(const float4*)&wsT[d][cc];
            ull v0 = *(const ull*)&vs[d][nn];
            ull v1 = *(const ull*)&vs[d][nn + 2];
            ull wp0 = pack2(w4.x, w4.x), wp1 = pack2(w4.y, w4.y);
            ull wp2 = pack2(w4.z, w4.z), wp3 = pack2(w4.w, w4.w);
            acc[0][0] = ffma2(wp0, v0, acc[0][0]); acc[0][1] = ffma2(wp0, v1, acc[0][1]);
            acc[1][0] = ffma2(wp1, v0, acc[1][0]); acc[1][1] = ffma2(wp1, v1, acc[1][1]);
            acc[2][0] = ffma2(wp2, v0, acc[2][0]); acc[2][1] = ffma2(wp2, v1, acc[2][1]);
            acc[3][0] = ffma2(wp3, v0, acc[3][0]); acc[3][1] = ffma2(wp3, v1, acc[3][1]);
        }
#pragma unroll
        for (int j = 0; j < 4; j++) {
            float v0, v1, v2, v3;
            unpack2(acc[j][0], v0, v1);
            unpack2(acc[j][1], v2, v3);
            *(float4*)(og + (size_t)(cc + j) * HWP + t * 128 + nn) = make_float4(v0, v1, v2, v3);
        }
        __syncthreads();
    }
}

// ---------------- launcher ----------------
extern "C" void kernel_launch(void* const* d_in, const int* in_sizes, int n_in,
                              void* d_out, int out_size) {
    const float* x        = (const float*)d_in[0];
    const float* mod_mult = (const float*)d_in[1];
    const float* mod_bias = (const float*)d_in[2];
    const float* qkv_w    = (const float*)d_in[3];
    const float* qkv_b    = (const float*)d_in[4];
    const float* pe_q_h   = (const float*)d_in[5];
    const float* pe_q_w   = (const float*)d_in[6];
    const float* pe_k_h   = (const float*)d_in[7];
    const float* pe_k_w   = (const float*)d_in[8];
    const float* pab      = (const float*)d_in[9];
    const float* pqb      = (const float*)d_in[10];
    float* out = (float*)d_out;

    __nv_bfloat16 *xh, *xl, *wh, *wl;
    float *biasH, *peW, *qkv, *lp, *wts;
    cudaGetSymbolAddress((void**)&xh, g_xh);
    cudaGetSymbolAddress((void**)&xl, g_xl);
    cudaGetSymbolAddress((void**)&wh, g_wh);
    cudaGetSymbolAddress((void**)&wl, g_wl);
    cudaGetSymbolAddress((void**)&biasH, g_biasH);
    cudaGetSymbolAddress((void**)&peW, g_peW);
    cudaGetSymbolAddress((void**)&qkv, g_qkv);
    cudaGetSymbolAddress((void**)&lp, g_lp);
    cudaGetSymbolAddress((void**)&wts, g_wts);

    cudaFuncSetAttribute(qkv_gemm_mma, cudaFuncAttributeMaxDynamicSharedMemorySize, GSMEM);

    silu_split_kernel<<<4096, 256>>>(x, pab, out, xh, xl);
    prep_kernel<<<CO, 64>>>(qkv_w, qkv_b, pqb, pe_q_h, pe_q_w, pe_k_h, pe_k_w,
                            wh, wl, biasH, peW);
    dim3 g3(HWP / 128, CO / 128, B_);
    qkv_gemm_mma<<<g3, 256, GSMEM>>>(xh, xl, wh, wl, biasH, peW,
                                     mod_mult, mod_bias, qkv);
    dim3 ga(8, NH, B_);
    attn_logits<<<ga, 256>>>(qkv, lp);
    attn_softmax<<<B_ * NH, 1024>>>(lp, wts);
    attn_out<<<ga, 256>>>(qkv, wts, out);
}